// round 7
// baseline (speedup 1.0000x reference)
#include <cuda_runtime.h>

#define NN 20000      // nodes
#define NE 100000     // edges
#define NF 64         // node feature dim (in) — 64 for every layer here
#define EFD 32        // edge feature dim
#define FH 128        // heads * out_dim = 2*64
#define NH 2          // heads
#define DH 64         // out dim per head

// ---------------- scratch (device globals) ----------------------------------
__device__ __align__(16) float g_elb[2][NN * NH]; // double-buffered el
__device__ __align__(16) float g_erb[2][NN * NH]; // double-buffered er
__device__ __align__(16) float g_h [NN * NF];
__device__ __align__(16) float g_h2[NN * NF];
__device__ __align__(16) float g_Wp[NF * FH];     // W_e2d^T @ Wn_dec0
__device__ __align__(16) float g_efs[NE * EFD];   // ef rows in CSR order
__device__ __align__(8)  float g_eeall[4][NE * NH]; // ee per layer, CSR order
__device__ int g_srcs[NE];                        // src in CSR order
// reduced attention weights per layer
__device__ float g_redl[4][NH * NF];
__device__ float g_redr[4][NH * NF];
__device__ float g_rede[4][NH * EFD];
// CSR (dst -> edges)
__device__ int g_deg[NN];        // zero-init at load; scan re-zeroes each call
__device__ int g_off[NN + 1];
__device__ int g_cur[NN];

// ================= CSR build ================================================
__global__ void hist_kernel(const int* __restrict__ dst)
{
    const int e = blockIdx.x * blockDim.x + threadIdx.x;
    if (e < NE) atomicAdd(&g_deg[dst[e]], 1);
}

#define SCAN_T 1024
#define CHUNK 20
__global__ __launch_bounds__(SCAN_T) void scan_kernel()
{
    __shared__ int sp[SCAN_T];
    const int t = threadIdx.x;
    const int base = t * CHUNK;
    int local[CHUNK];
    int sum = 0;
#pragma unroll
    for (int i = 0; i < CHUNK; i++) {
        const int idx = base + i;
        local[i] = sum;
        int d = 0;
        if (idx < NN) { d = g_deg[idx]; g_deg[idx] = 0; }  // reset for next call
        sum += d;
    }
    sp[t] = sum;
    __syncthreads();
    for (int o = 1; o < SCAN_T; o <<= 1) {
        int v = 0;
        if (t >= o) v = sp[t - o];
        __syncthreads();
        if (t >= o) sp[t] += v;
        __syncthreads();
    }
    const int basesum = sp[t] - sum;
#pragma unroll
    for (int i = 0; i < CHUNK; i++) {
        const int idx = base + i;
        if (idx < NN) {
            const int o = basesum + local[i];
            g_off[idx] = o;
            g_cur[idx] = o;
        }
    }
    if (t == SCAN_T - 1) g_off[NN] = basesum + sum;
}

// scatter + gather + 4-layer ee, all in one pass over edges
__global__ __launch_bounds__(256) void scatterF_kernel(
        const int* __restrict__ dst, const int* __restrict__ src,
        const float* __restrict__ ef)
{
    __shared__ float srd[4][NH * EFD];
    const int t = threadIdx.x;
    if (t < 4 * NH * EFD) ((float*)srd)[t] = ((const float*)g_rede)[t];
    __syncthreads();

    const int e = blockIdx.x * blockDim.x + t;
    if (e >= NE) return;
    const int pos = atomicAdd(&g_cur[dst[e]], 1);
    g_srcs[pos] = src[e];

    float r[EFD];
#pragma unroll
    for (int q = 0; q < EFD / 4; q++) {
        const float4 v = __ldg((const float4*)&ef[(size_t)e * EFD + q * 4]);
        r[q * 4 + 0] = v.x; r[q * 4 + 1] = v.y; r[q * 4 + 2] = v.z; r[q * 4 + 3] = v.w;
        *(float4*)&g_efs[(size_t)pos * EFD + q * 4] = v;
    }
#pragma unroll
    for (int lid = 0; lid < 4; lid++) {
        float v0 = 0.f, v1 = 0.f;
#pragma unroll
        for (int k = 0; k < EFD; k++) {
            v0 = fmaf(r[k], srd[lid][k], v0);
            v1 = fmaf(r[k], srd[lid][EFD + k], v1);
        }
        *(float2*)&g_eeall[lid][(size_t)pos * NH] = make_float2(v0, v1);
    }
}

// ================= weight preprocessing =====================================
__global__ __launch_bounds__(256) void wfuse_kernel(
        const float* __restrict__ W_e2d, const float* __restrict__ Wn_dec0)
{
    const int i = blockIdx.x * blockDim.x + threadIdx.x;   // m*128 + c
    const int m = i >> 7, c = i & 127;
    float v = 0.f;
#pragma unroll
    for (int k = 0; k < NF; k++)
        v = fmaf(W_e2d[k * NF + m], Wn_dec0[k * FH + c], v);
    g_Wp[m * FH + c] = v;
}

struct PrepParams {
    const float *Wn[4], *We[4], *al[4], *ar[4], *ae[4];
};

__global__ __launch_bounds__(256) void prep_kernel(PrepParams pp)
{
    const int lid = blockIdx.x;
    const int t = threadIdx.x;
    const float* Wn = pp.Wn[lid];
    const float* We = pp.We[lid];
    {   // redl / redr: 2 types * 2 heads * 64 k
        const int type = t >> 7, r = t & 127;
        const int h = r >> 6, k = r & 63;
        const float* a = type ? pp.ar[lid] : pp.al[lid];
        float v = 0.f;
#pragma unroll
        for (int d = 0; d < DH; d++)
            v = fmaf(Wn[k * FH + h * DH + d], a[h * DH + d], v);
        (type ? g_redr : g_redl)[lid][h * NF + k] = v;
    }
    if (t < NH * EFD) {   // rede
        const int h = t >> 5, k = t & 31;
        const float* ae = pp.ae[lid];
        float v = 0.f;
#pragma unroll
        for (int d = 0; d < DH; d++)
            v = fmaf(We[k * FH + h * DH + d], ae[h * DH + d], v);
        g_rede[lid][h * EFD + k] = v;
    }
}

// el/er for layer 0
__global__ __launch_bounds__(128) void nodeattn_kernel(const float* __restrict__ x)
{
    const int c = threadIdx.x;
    const int n0 = blockIdx.x * 32;
    __shared__ float sx[32][NF + 1];
    for (int i = c; i < 32 * NF; i += 128)
        sx[i >> 6][i & 63] = x[(size_t)n0 * NF + i];
    __syncthreads();
    const int type = c >> 6, h = (c >> 5) & 1, i = c & 31;
    const float* rd = (type ? g_redr : g_redl)[0] + h * NF;
    float v = 0.f;
#pragma unroll
    for (int k = 0; k < NF; k++) v = fmaf(sx[i][k], rd[k], v);
    (type ? g_erb : g_elb)[0][(n0 + i) * NH + h] = v;
}

// ================= fused layer kernel ========================================
// 512 threads, 16 nodes per block. Phases:
//   A) stage Wn/We/b in smem; warp-per-node edge loop (batched x4 for MLP)
//      accumulating xs (weighted x sums), us (weighted ef sums), s (denoms)
//   B) block GEMM: t = ((xs_h@Wn_h)+(us_h@We_h))/s_h + b
//   C) head-mean -> hout; next-layer el/er from fresh output rows
__global__ __launch_bounds__(512) void layer_kernel(
        const float* __restrict__ x,
        const float* __restrict__ Wn, const float* __restrict__ We,
        const float* __restrict__ b,
        const float* __restrict__ el_in, const float* __restrict__ er_in,
        float* __restrict__ el_out, float* __restrict__ er_out,
        int lid, int last, float* __restrict__ hout)
{
    extern __shared__ float sm[];
    float* sWn = sm;              // 8192
    float* sWe = sm + 8192;       // 4096
    float* sb  = sm + 12288;      // 128
    float* sxs = sm + 12416;      // 16*128
    float* sus = sm + 14464;      // 16*64
    float* sss = sm + 15488;      // 16*2
    float* st  = sm + 15520;      // 16*128

    const int t = threadIdx.x;
    for (int i = t; i < 2048; i += 512) ((float4*)sWn)[i] = __ldg(&((const float4*)Wn)[i]);
    for (int i = t; i < 1024; i += 512) ((float4*)sWe)[i] = __ldg(&((const float4*)We)[i]);
    if (t < 128) sb[t] = b[t];

    const int wid = t >> 5, lane = t & 31;
    const int n0 = blockIdx.x * 16;
    const int n = n0 + wid;
    const float2 er2 = *(const float2*)&er_in[n * NH];
    const int start = g_off[n], end = g_off[n + 1];
    const int xoff = (lane & 15) * 4;
    const float* eep = g_eeall[lid];

    float4 xa = make_float4(0.f, 0.f, 0.f, 0.f);
    float u0 = 0.f, u1 = 0.f, s0 = 0.f, s1 = 0.f;

    int j = start;
    for (; j + 4 <= end; j += 4) {
        int sn[4]; float2 ee[4], el[4]; float4 xv[4]; float ev[4];
#pragma unroll
        for (int q = 0; q < 4; q++) sn[q] = g_srcs[j + q];
#pragma unroll
        for (int q = 0; q < 4; q++) {
            ee[q] = *(const float2*)&eep[(size_t)(j + q) * NH];
            el[q] = *(const float2*)&el_in[sn[q] * NH];
            xv[q] = __ldg((const float4*)&x[(size_t)sn[q] * NF + xoff]);
            ev[q] = g_efs[(size_t)(j + q) * EFD + lane];
        }
#pragma unroll
        for (int q = 0; q < 4; q++) {
            float l0 = el[q].x + er2.x + ee[q].x;
            float l1 = el[q].y + er2.y + ee[q].y;
            l0 = (l0 > 0.f) ? l0 : 0.2f * l0;
            l1 = (l1 > 0.f) ? l1 : 0.2f * l1;
            const float p0 = __expf(l0), p1 = __expf(l1);
            s0 += p0; s1 += p1;
            const float ph = (lane < 16) ? p0 : p1;
            xa.x = fmaf(xv[q].x, ph, xa.x);
            xa.y = fmaf(xv[q].y, ph, xa.y);
            xa.z = fmaf(xv[q].z, ph, xa.z);
            xa.w = fmaf(xv[q].w, ph, xa.w);
            u0 = fmaf(ev[q], p0, u0);
            u1 = fmaf(ev[q], p1, u1);
        }
    }
    for (; j < end; j++) {
        const int sn = g_srcs[j];
        const float2 ee = *(const float2*)&eep[(size_t)j * NH];
        const float2 el2 = *(const float2*)&el_in[sn * NH];
        float l0 = el2.x + er2.x + ee.x;
        float l1 = el2.y + er2.y + ee.y;
        l0 = (l0 > 0.f) ? l0 : 0.2f * l0;
        l1 = (l1 > 0.f) ? l1 : 0.2f * l1;
        const float p0 = __expf(l0), p1 = __expf(l1);
        s0 += p0; s1 += p1;
        const float ph = (lane < 16) ? p0 : p1;
        const float4 x4 = __ldg((const float4*)&x[(size_t)sn * NF + xoff]);
        const float efv = g_efs[(size_t)j * EFD + lane];
        xa.x = fmaf(x4.x, ph, xa.x);
        xa.y = fmaf(x4.y, ph, xa.y);
        xa.z = fmaf(x4.z, ph, xa.z);
        xa.w = fmaf(x4.w, ph, xa.w);
        u0 = fmaf(efv, p0, u0);
        u1 = fmaf(efv, p1, u1);
    }

    *(float4*)&sxs[wid * FH + lane * 4] = xa;   // [0:64)=h0, [64:128)=h1
    sus[wid * 64 + lane] = u0;
    sus[wid * 64 + 32 + lane] = u1;
    if (lane == 0) { sss[wid * 2 + 0] = s0; sss[wid * 2 + 1] = s1; }
    __syncthreads();

    // B) block GEMM over smem
#pragma unroll
    for (int rep = 0; rep < 4; rep++) {
        const int idx = rep * 512 + t;          // 16*128 outputs
        const int i = idx >> 7, c = idx & 127, h = c >> 6;
        const float* xsr = sxs + i * FH + h * 64;
        float a = 0.f;
#pragma unroll
        for (int k = 0; k < NF; k++) a = fmaf(xsr[k], sWn[k * FH + c], a);
        const float* usr = sus + i * 64 + h * 32;
        float uu = 0.f;
#pragma unroll
        for (int k = 0; k < EFD; k++) uu = fmaf(usr[k], sWe[k * FH + c], uu);
        const float s = sss[i * 2 + h];
        const float inv = (s > 0.f) ? 1.f / s : 0.f;   // deg-0 node -> msg = 0
        st[idx] = fmaf(a + uu, inv, sb[c]);
    }
    __syncthreads();

    // C) head mean -> hout
#pragma unroll
    for (int rep = 0; rep < 2; rep++) {
        const int idx = rep * 512 + t;          // 16*64 outputs
        const int i = idx >> 6, d = idx & 63;
        hout[(size_t)(n0 + i) * DH + d] = 0.5f * (st[i * FH + d] + st[i * FH + 64 + d]);
    }
    // next-layer el/er from output rows
    if (!last && t < 64) {
        const int type = t >> 5, h = (t >> 4) & 1, i = t & 15;
        const float* rd = (type ? g_redr : g_redl)[lid + 1] + h * NF;
        float v = 0.f;
#pragma unroll
        for (int d = 0; d < DH; d++)
            v = fmaf(0.5f * (st[i * FH + d] + st[i * FH + 64 + d]), rd[d], v);
        (type ? er_out : el_out)[(n0 + i) * NH + h] = v;
    }
}

// ---------------- host-side driver ------------------------------------------
#define LAYER_SMEM (17568 * 4)

extern "C" void kernel_launch(void* const* d_in, const int* in_sizes, int n_in,
                              void* d_out, int out_size)
{
    const float* x   = (const float*)d_in[0];
    const float* e   = (const float*)d_in[1];
    const int*   src = (const int*)  d_in[2];
    const int*   dst = (const int*)  d_in[3];

    // Only the LAST snapshot contributes to the output (decoded[-1]).
    const int S = in_sizes[0] / (NN * NF);
    const float* xs = x   + (size_t)(S - 1) * NN * NF;
    const float* es = e   + (size_t)(S - 1) * NE * EFD;
    const int*   ss = src + (size_t)(S - 1) * NE;
    const int*   ds = dst + (size_t)(S - 1) * NE;

    void *ph = nullptr, *ph2 = nullptr, *pwp = nullptr, *pel = nullptr, *per = nullptr;
    cudaGetSymbolAddress(&ph,  g_h);
    cudaGetSymbolAddress(&ph2, g_h2);
    cudaGetSymbolAddress(&pwp, g_Wp);
    cudaGetSymbolAddress(&pel, g_elb);
    cudaGetSymbolAddress(&per, g_erb);
    float* h  = (float*)ph;
    float* h2 = (float*)ph2;
    const float* Wp = (const float*)pwp;
    float* elb[2] = { (float*)pel, (float*)pel + NN * NH };
    float* erb[2] = { (float*)per, (float*)per + NN * NH };

    cudaFuncSetAttribute(layer_kernel, cudaFuncAttributeMaxDynamicSharedMemorySize,
                         LAYER_SMEM);

    // Input order (setup_inputs dict insertion order):
    //   0:x 1:e 2:src 3:dst, 4..9:enc0{Wn,We,al,ar,ae,b}, 10..15:enc1,
    //   16..21:dec0, 22..27:dec1, 28:W_e2d
    const float* P[29];
    for (int i = 4; i <= 28; i++) P[i] = (const float*)d_in[i];

    hist_kernel<<<(NE + 255) / 256, 256>>>(ds);
    scan_kernel<<<1, SCAN_T>>>();
    wfuse_kernel<<<NF * FH / 256, 256>>>(P[28], P[16]);
    PrepParams pp;
    pp.Wn[0] = P[4];  pp.We[0] = P[5];  pp.al[0] = P[6];  pp.ar[0] = P[7];  pp.ae[0] = P[8];
    pp.Wn[1] = P[10]; pp.We[1] = P[11]; pp.al[1] = P[12]; pp.ar[1] = P[13]; pp.ae[1] = P[14];
    pp.Wn[2] = Wp;    pp.We[2] = P[17]; pp.al[2] = P[18]; pp.ar[2] = P[19]; pp.ae[2] = P[20];
    pp.Wn[3] = P[22]; pp.We[3] = P[23]; pp.al[3] = P[24]; pp.ar[3] = P[25]; pp.ae[3] = P[26];
    prep_kernel<<<4, 256>>>(pp);
    scatterF_kernel<<<(NE + 255) / 256, 256>>>(ds, ss, es);
    nodeattn_kernel<<<NN / 32, 128>>>(xs);

    // layers: lid reads el/er buffer lid&1, writes buffer (lid+1)&1
    layer_kernel<<<NN / 16, 512, LAYER_SMEM>>>(
        xs, P[4], P[5], P[9], elb[0], erb[0], elb[1], erb[1], 0, 0, h);
    layer_kernel<<<NN / 16, 512, LAYER_SMEM>>>(
        h, P[10], P[11], P[15], elb[1], erb[1], elb[0], erb[0], 1, 0, h2);
    layer_kernel<<<NN / 16, 512, LAYER_SMEM>>>(
        h2, Wp, P[17], P[21], elb[0], erb[0], elb[1], erb[1], 2, 0, h);
    layer_kernel<<<NN / 16, 512, LAYER_SMEM>>>(
        h, P[22], P[23], P[27], elb[1], erb[1], elb[0], erb[0], 3, 1, (float*)d_out);
}

// round 8
// speedup vs baseline: 1.0735x; 1.0735x over previous
#include <cuda_runtime.h>

#define NN 20000      // nodes
#define NE 100000     // edges
#define NF 64         // node feature dim (in) — 64 for every layer here
#define EFD 32        // edge feature dim
#define FH 128        // heads * out_dim = 2*64
#define NH 2          // heads
#define DH 64         // out dim per head

// ---------------- scratch (device globals) ----------------------------------
__device__ __align__(16) float g_elb[2][NN * NH]; // double-buffered el
__device__ __align__(16) float g_erb[2][NN * NH]; // double-buffered er
__device__ __align__(16) float g_xs[NN * FH];     // per-node weighted x sums
__device__ __align__(16) float g_us[NN * 2 * EFD];// per-node weighted ef sums
__device__ __align__(16) float g_ss[NN * NH];     // softmax denominators
__device__ __align__(16) float g_h [NN * NF];
__device__ __align__(16) float g_h2[NN * NF];
__device__ __align__(16) float g_Wp[NF * FH];     // W_e2d^T @ Wn_dec0
__device__ __align__(16) float g_efs[NE * EFD];   // ef rows in CSR order
__device__ __align__(8)  float g_eeall[4][NE * NH]; // ee per layer, CSR order
__device__ int g_srcs[NE];                        // src in CSR order
// reduced attention weights per layer
__device__ float g_redl[4][NH * NF];
__device__ float g_redr[4][NH * NF];
__device__ float g_rede[4][NH * EFD];
// CSR (dst -> edges)
__device__ int g_deg[NN];        // zero-init at load; scan re-zeroes each call
__device__ int g_off[NN + 1];
__device__ int g_cur[NN];

// ================= CSR build ================================================
__global__ void hist_kernel(const int* __restrict__ dst)
{
    const int e = blockIdx.x * blockDim.x + threadIdx.x;
    if (e < NE) atomicAdd(&g_deg[dst[e]], 1);
}

#define SCAN_T 1024
#define CHUNK 20
__global__ __launch_bounds__(SCAN_T) void scan_kernel()
{
    __shared__ int sp[SCAN_T];
    const int t = threadIdx.x;
    const int base = t * CHUNK;
    int local[CHUNK];
    int sum = 0;
#pragma unroll
    for (int i = 0; i < CHUNK; i++) {
        const int idx = base + i;
        local[i] = sum;
        int d = 0;
        if (idx < NN) { d = g_deg[idx]; g_deg[idx] = 0; }  // reset for next call
        sum += d;
    }
    sp[t] = sum;
    __syncthreads();
    for (int o = 1; o < SCAN_T; o <<= 1) {
        int v = 0;
        if (t >= o) v = sp[t - o];
        __syncthreads();
        if (t >= o) sp[t] += v;
        __syncthreads();
    }
    const int basesum = sp[t] - sum;
#pragma unroll
    for (int i = 0; i < CHUNK; i++) {
        const int idx = base + i;
        if (idx < NN) {
            const int o = basesum + local[i];
            g_off[idx] = o;
            g_cur[idx] = o;
        }
    }
    if (t == SCAN_T - 1) g_off[NN] = basesum + sum;
}

// scatter + gather + 4-layer ee, all in one pass over edges
__global__ __launch_bounds__(256) void scatterF_kernel(
        const int* __restrict__ dst, const int* __restrict__ src,
        const float* __restrict__ ef)
{
    __shared__ float srd[4][NH * EFD];
    const int t = threadIdx.x;
    if (t < 4 * NH * EFD) ((float*)srd)[t] = ((const float*)g_rede)[t];
    __syncthreads();

    const int e = blockIdx.x * blockDim.x + t;
    if (e >= NE) return;
    const int pos = atomicAdd(&g_cur[dst[e]], 1);
    g_srcs[pos] = src[e];

    float r[EFD];
#pragma unroll
    for (int q = 0; q < EFD / 4; q++) {
        const float4 v = __ldg((const float4*)&ef[(size_t)e * EFD + q * 4]);
        r[q * 4 + 0] = v.x; r[q * 4 + 1] = v.y; r[q * 4 + 2] = v.z; r[q * 4 + 3] = v.w;
        *(float4*)&g_efs[(size_t)pos * EFD + q * 4] = v;
    }
#pragma unroll
    for (int lid = 0; lid < 4; lid++) {
        float v0 = 0.f, v1 = 0.f;
#pragma unroll
        for (int k = 0; k < EFD; k++) {
            v0 = fmaf(r[k], srd[lid][k], v0);
            v1 = fmaf(r[k], srd[lid][EFD + k], v1);
        }
        *(float2*)&g_eeall[lid][(size_t)pos * NH] = make_float2(v0, v1);
    }
}

// ================= weight preprocessing =====================================
__global__ __launch_bounds__(256) void wfuse_kernel(
        const float* __restrict__ W_e2d, const float* __restrict__ Wn_dec0)
{
    const int i = blockIdx.x * blockDim.x + threadIdx.x;   // m*128 + c
    const int m = i >> 7, c = i & 127;
    float v = 0.f;
#pragma unroll
    for (int k = 0; k < NF; k++)
        v = fmaf(W_e2d[k * NF + m], Wn_dec0[k * FH + c], v);
    g_Wp[m * FH + c] = v;
}

struct PrepParams {
    const float *Wn[4], *We[4], *al[4], *ar[4], *ae[4];
};

// grid = 12: blockIdx.x = lid*3 + mat (0=redl, 1=redr, 2=rede), 128 threads
__global__ __launch_bounds__(128) void prep_kernel(PrepParams pp)
{
    const int lid = blockIdx.x / 3, mat = blockIdx.x % 3;
    const int t = threadIdx.x;
    if (mat < 2) {       // redl / redr: 128 tasks = 2 heads * 64 k
        const int h = t >> 6, k = t & 63;
        const float* Wn = pp.Wn[lid];
        const float* a = mat ? pp.ar[lid] : pp.al[lid];
        float v = 0.f;
#pragma unroll
        for (int d = 0; d < DH; d++)
            v = fmaf(Wn[k * FH + h * DH + d], a[h * DH + d], v);
        (mat ? g_redr : g_redl)[lid][h * NF + k] = v;
    } else if (t < NH * EFD) {   // rede: 64 tasks
        const int h = t >> 5, k = t & 31;
        const float* We = pp.We[lid];
        const float* ae = pp.ae[lid];
        float v = 0.f;
#pragma unroll
        for (int d = 0; d < DH; d++)
            v = fmaf(We[k * FH + h * DH + d], ae[h * DH + d], v);
        g_rede[lid][h * EFD + k] = v;
    }
}

// el/er for layer 0 only (subsequent layers get el/er from fin's epilogue)
__global__ __launch_bounds__(128) void nodeattn_kernel(const float* __restrict__ x)
{
    const int c = threadIdx.x;
    const int n0 = blockIdx.x * 32;
    __shared__ float sx[32][NF + 1];
    for (int i = c; i < 32 * NF; i += 128)
        sx[i >> 6][i & 63] = x[(size_t)n0 * NF + i];
    __syncthreads();
    const int type = c >> 6, h = (c >> 5) & 1, i = c & 31;
    const float* rd = (type ? g_redr : g_redl)[0] + h * NF;
    float v = 0.f;
#pragma unroll
    for (int k = 0; k < NF; k++) v = fmaf(sx[i][k], rd[k], v);
    (type ? g_erb : g_elb)[0][(n0 + i) * NH + h] = v;
}

// ================= per-layer kernels ========================================

// fused softmax + weighted-input aggregation. warp per dst node, x4 batched.
__global__ __launch_bounds__(256) void agg_kernel(
        const float* __restrict__ x,
        const float* __restrict__ el_in, const float* __restrict__ er_in,
        int lid)
{
    const int t = threadIdx.x;
    const int wid = t >> 5, lane = t & 31;
    const int n = blockIdx.x * 8 + wid;
    const float2 er2 = *(const float2*)&er_in[n * NH];
    const int start = g_off[n], end = g_off[n + 1];
    const int xoff = (lane & 15) * 4;
    const float* eep = g_eeall[lid];

    float4 xa = make_float4(0.f, 0.f, 0.f, 0.f);
    float u0 = 0.f, u1 = 0.f, s0 = 0.f, s1 = 0.f;

    int j = start;
    for (; j + 4 <= end; j += 4) {
        int sn[4]; float2 ee[4], el[4]; float4 xv[4]; float ev[4];
#pragma unroll
        for (int q = 0; q < 4; q++) sn[q] = g_srcs[j + q];
#pragma unroll
        for (int q = 0; q < 4; q++) {
            ee[q] = *(const float2*)&eep[(size_t)(j + q) * NH];
            el[q] = *(const float2*)&el_in[sn[q] * NH];
            xv[q] = __ldg((const float4*)&x[(size_t)sn[q] * NF + xoff]);
            ev[q] = g_efs[(size_t)(j + q) * EFD + lane];
        }
#pragma unroll
        for (int q = 0; q < 4; q++) {
            float l0 = el[q].x + er2.x + ee[q].x;
            float l1 = el[q].y + er2.y + ee[q].y;
            l0 = (l0 > 0.f) ? l0 : 0.2f * l0;
            l1 = (l1 > 0.f) ? l1 : 0.2f * l1;
            const float p0 = __expf(l0), p1 = __expf(l1);
            s0 += p0; s1 += p1;
            const float ph = (lane < 16) ? p0 : p1;
            xa.x = fmaf(xv[q].x, ph, xa.x);
            xa.y = fmaf(xv[q].y, ph, xa.y);
            xa.z = fmaf(xv[q].z, ph, xa.z);
            xa.w = fmaf(xv[q].w, ph, xa.w);
            u0 = fmaf(ev[q], p0, u0);
            u1 = fmaf(ev[q], p1, u1);
        }
    }
    for (; j < end; j++) {
        const int sn = g_srcs[j];
        const float2 ee = *(const float2*)&eep[(size_t)j * NH];
        const float2 el2 = *(const float2*)&el_in[sn * NH];
        float l0 = el2.x + er2.x + ee.x;
        float l1 = el2.y + er2.y + ee.y;
        l0 = (l0 > 0.f) ? l0 : 0.2f * l0;
        l1 = (l1 > 0.f) ? l1 : 0.2f * l1;
        const float p0 = __expf(l0), p1 = __expf(l1);
        s0 += p0; s1 += p1;
        const float ph = (lane < 16) ? p0 : p1;
        const float4 x4 = __ldg((const float4*)&x[(size_t)sn * NF + xoff]);
        const float efv = g_efs[(size_t)j * EFD + lane];
        xa.x = fmaf(x4.x, ph, xa.x);
        xa.y = fmaf(x4.y, ph, xa.y);
        xa.z = fmaf(x4.z, ph, xa.z);
        xa.w = fmaf(x4.w, ph, xa.w);
        u0 = fmaf(efv, p0, u0);
        u1 = fmaf(efv, p1, u1);
    }

    *(float4*)&g_xs[(size_t)n * FH + lane * 4] = xa;   // [0:64)=h0, [64:128)=h1
    g_us[n * 2 * EFD + lane] = u0;
    g_us[n * 2 * EFD + EFD + lane] = u1;
    if (lane == 0) {
        g_ss[n * NH + 0] = s0;
        g_ss[n * NH + 1] = s1;
    }
}

// finalize: out = ((xs_h @ Wn_h) + (u_h @ We_h))/s_h + b, mean over heads;
// epilogue computes next layer's el/er from the fresh output rows.
__global__ __launch_bounds__(128) void fin_kernel(
        const float* __restrict__ Wn, const float* __restrict__ We,
        const float* __restrict__ b,
        float* __restrict__ el_out, float* __restrict__ er_out,
        int lid, int last, float* __restrict__ hout)
{
    const int c = threadIdx.x;                 // c = h*64 + d
    const int n0 = blockIdx.x * 16;
    const int h = c >> 6;
    float wn[NF];
#pragma unroll
    for (int k = 0; k < NF; k++) wn[k] = Wn[k * FH + c];
    float we[EFD];
#pragma unroll
    for (int k = 0; k < EFD; k++) we[k] = We[k * FH + c];
    const float bc = b[c];

    __shared__ float sxs[16][FH];
    __shared__ float sus[16][2 * EFD];
    __shared__ float sss[16][NH];
    __shared__ float st [16][FH];
    for (int i = c; i < 16 * FH; i += 128) sxs[i >> 7][i & 127] = g_xs[(size_t)n0 * FH + i];
    for (int i = c; i < 16 * 2 * EFD; i += 128) sus[i >> 6][i & 63] = g_us[n0 * 2 * EFD + i];
    if (c < 16 * NH) sss[c >> 1][c & 1] = g_ss[n0 * NH + c];
    __syncthreads();

#pragma unroll 2
    for (int i = 0; i < 16; i++) {
        float a = 0.f;
#pragma unroll
        for (int k = 0; k < NF; k++) a = fmaf(sxs[i][h * NF + k], wn[k], a);
        float uu = 0.f;
#pragma unroll
        for (int k = 0; k < EFD; k++) uu = fmaf(sus[i][h * EFD + k], we[k], uu);
        const float s = sss[i][h];
        const float inv = (s > 0.f) ? 1.f / s : 0.f;   // deg-0 node -> msg = 0
        st[i][c] = fmaf(a + uu, inv, bc);
    }
    __syncthreads();

    for (int i = c; i < 16 * DH; i += 128) {
        const int ni = i >> 6, d = i & 63;
        hout[(size_t)(n0 + ni) * DH + d] = 0.5f * (st[ni][d] + st[ni][DH + d]);
    }
    // next-layer el/er from output rows (64 tasks: type x head x 16 nodes)
    if (!last && c < 64) {
        const int type = c >> 5, hh = (c >> 4) & 1, i = c & 15;
        const float* rd = (type ? g_redr : g_redl)[lid + 1] + hh * NF;
        float v = 0.f;
#pragma unroll
        for (int d = 0; d < DH; d++)
            v = fmaf(0.5f * (st[i][d] + st[i][DH + d]), rd[d], v);
        (type ? er_out : el_out)[(n0 + i) * NH + hh] = v;
    }
}

// ---------------- host-side driver ------------------------------------------
extern "C" void kernel_launch(void* const* d_in, const int* in_sizes, int n_in,
                              void* d_out, int out_size)
{
    const float* x   = (const float*)d_in[0];
    const float* e   = (const float*)d_in[1];
    const int*   src = (const int*)  d_in[2];
    const int*   dst = (const int*)  d_in[3];

    // Only the LAST snapshot contributes to the output (decoded[-1]).
    const int S = in_sizes[0] / (NN * NF);
    const float* xs = x   + (size_t)(S - 1) * NN * NF;
    const float* es = e   + (size_t)(S - 1) * NE * EFD;
    const int*   ss = src + (size_t)(S - 1) * NE;
    const int*   ds = dst + (size_t)(S - 1) * NE;

    void *ph = nullptr, *ph2 = nullptr, *pwp = nullptr, *pel = nullptr, *per = nullptr;
    cudaGetSymbolAddress(&ph,  g_h);
    cudaGetSymbolAddress(&ph2, g_h2);
    cudaGetSymbolAddress(&pwp, g_Wp);
    cudaGetSymbolAddress(&pel, g_elb);
    cudaGetSymbolAddress(&per, g_erb);
    float* h  = (float*)ph;
    float* h2 = (float*)ph2;
    const float* Wp = (const float*)pwp;
    float* elb[2] = { (float*)pel, (float*)pel + NN * NH };
    float* erb[2] = { (float*)per, (float*)per + NN * NH };

    // Input order (setup_inputs dict insertion order):
    //   0:x 1:e 2:src 3:dst, 4..9:enc0{Wn,We,al,ar,ae,b}, 10..15:enc1,
    //   16..21:dec0, 22..27:dec1, 28:W_e2d
    const float* P[29];
    for (int i = 4; i <= 28; i++) P[i] = (const float*)d_in[i];

    hist_kernel<<<(NE + 255) / 256, 256>>>(ds);
    scan_kernel<<<1, SCAN_T>>>();
    wfuse_kernel<<<NF * FH / 256, 256>>>(P[28], P[16]);
    PrepParams pp;
    pp.Wn[0] = P[4];  pp.We[0] = P[5];  pp.al[0] = P[6];  pp.ar[0] = P[7];  pp.ae[0] = P[8];
    pp.Wn[1] = P[10]; pp.We[1] = P[11]; pp.al[1] = P[12]; pp.ar[1] = P[13]; pp.ae[1] = P[14];
    pp.Wn[2] = Wp;    pp.We[2] = P[17]; pp.al[2] = P[18]; pp.ar[2] = P[19]; pp.ae[2] = P[20];
    pp.Wn[3] = P[22]; pp.We[3] = P[23]; pp.al[3] = P[24]; pp.ar[3] = P[25]; pp.ae[3] = P[26];
    prep_kernel<<<12, 128>>>(pp);
    scatterF_kernel<<<(NE + 255) / 256, 256>>>(ds, ss, es);
    nodeattn_kernel<<<NN / 32, 128>>>(xs);

    // layer 0 (enc0)
    agg_kernel<<<NN / 8, 256>>>(xs, elb[0], erb[0], 0);
    fin_kernel<<<NN / 16, 128>>>(P[4], P[5], P[9], elb[1], erb[1], 0, 0, h);
    // layer 1 (enc1)
    agg_kernel<<<NN / 8, 256>>>(h, elb[1], erb[1], 1);
    fin_kernel<<<NN / 16, 128>>>(P[10], P[11], P[15], elb[0], erb[0], 1, 0, h2);
    // layer 2 (dec0, e2d fused via Wp)
    agg_kernel<<<NN / 8, 256>>>(h2, elb[0], erb[0], 2);
    fin_kernel<<<NN / 16, 128>>>(Wp, P[17], P[21], elb[1], erb[1], 2, 0, h);
    // layer 3 (dec1)
    agg_kernel<<<NN / 8, 256>>>(h, elb[1], erb[1], 3);
    fin_kernel<<<NN / 16, 128>>>(P[22], P[23], P[27], elb[0], erb[0], 3, 1, (float*)d_out);
}

// round 9
// speedup vs baseline: 1.0815x; 1.0074x over previous
#include <cuda_runtime.h>

#define NN 20000      // nodes
#define NE 100000     // edges
#define NF 64         // node feature dim (in) — 64 for every layer here
#define EFD 32        // edge feature dim
#define FH 128        // heads * out_dim = 2*64
#define NH 2          // heads
#define DH 64         // out dim per head

// ---------------- scratch (device globals) ----------------------------------
__device__ __align__(16) float g_elb[2][NN * NH]; // double-buffered el
__device__ __align__(16) float g_erb[2][NN * NH]; // double-buffered er
__device__ __align__(16) float g_xs[NN * FH];     // per-node weighted x sums
__device__ __align__(16) float g_us[NN * 2 * EFD];// per-node weighted ef sums
__device__ __align__(16) float g_ss[NN * NH];     // softmax denominators
__device__ __align__(16) float g_h [NN * NF];
__device__ __align__(16) float g_h2[NN * NF];
__device__ __align__(16) float g_Wp[NF * FH];     // W_e2d^T @ Wn_dec0
__device__ __align__(16) float g_efs[NE * EFD];   // ef rows in CSR order
__device__ __align__(8)  float g_eeall[4][NE * NH]; // ee per layer, CSR order
__device__ int g_srcs[NE];                        // src in CSR order
// reduced attention weights per layer
__device__ float g_redl[4][NH * NF];
__device__ float g_redr[4][NH * NF];
__device__ float g_rede[4][NH * EFD];
// CSR (dst -> edges)
__device__ int g_deg[NN];        // zero-init at load; scan re-zeroes each call
__device__ int g_off[NN + 1];
__device__ int g_cur[NN];

struct PrepParams {
    const float *Wn[4], *We[4], *al[4], *ar[4], *ae[4];
    const float* We2d;
};

// ================= pre1: hist + wfuse + prep (fused) ========================
#define B_HIST 391     // ceil(NE/256)
#define B_WF   32      // NF*FH/256
#define B_PREP 12      // 4 layers * 3 matrices
__global__ __launch_bounds__(256) void pre1_kernel(
        const int* __restrict__ dst, PrepParams pp)
{
    const int t = threadIdx.x;
    const int b = blockIdx.x;
    if (b < B_HIST) {                              // ---- histogram
        const int e = b * 256 + t;
        if (e < NE) atomicAdd(&g_deg[dst[e]], 1);
    } else if (b < B_HIST + B_WF) {                // ---- Wp = W_e2d^T @ Wn_dec0
        const int i = (b - B_HIST) * 256 + t;      // m*128 + c
        const int m = i >> 7, c = i & 127;
        float v = 0.f;
#pragma unroll
        for (int k = 0; k < NF; k++)
            v = fmaf(pp.We2d[k * NF + m], pp.Wn[2][k * FH + c], v);
        g_Wp[m * FH + c] = v;
    } else {                                       // ---- reduced attn weights
        const int bid2 = b - B_HIST - B_WF;
        const int lid = bid2 / 3, mat = bid2 % 3;
        __shared__ float stt[128];
        if (mat < 2) {                             // redl / redr
            const float* a = mat ? pp.ar[lid] : pp.al[lid];
            float v = 0.f;
            if (t < 128) {
                const int h = t >> 6, k = t & 63;
#pragma unroll
                for (int d = 0; d < DH; d++)
                    v = fmaf(pp.Wn[lid][k * FH + h * DH + d], a[h * DH + d], v);
                if (lid == 2) stt[t] = v;          // two-step for dec0 (e2d fused)
                else (mat ? g_redr : g_redl)[lid][(t >> 6) * NF + (t & 63)] = v;
            }
            if (lid == 2) {
                __syncthreads();
                if (t < 128) {
                    const int h = t >> 6, m = t & 63;
                    float w = 0.f;
#pragma unroll
                    for (int k = 0; k < NF; k++)
                        w = fmaf(pp.We2d[k * NF + m], stt[h * 64 + k], w);
                    (mat ? g_redr : g_redl)[2][h * NF + m] = w;
                }
            }
        } else if (t < NH * EFD) {                 // rede
            const int h = t >> 5, k = t & 31;
            float v = 0.f;
#pragma unroll
            for (int d = 0; d < DH; d++)
                v = fmaf(pp.We[lid][k * FH + h * DH + d], pp.ae[lid][h * DH + d], v);
            g_rede[lid][h * EFD + k] = v;
        }
    }
}

// ================= scan: smem-staged coalesced prefix sum ====================
#define SCAN_T 1024
#define CHUNK 20
__global__ __launch_bounds__(SCAN_T) void scan_kernel()
{
    extern __shared__ int si[];
    int* sdeg = si;                 // NN
    int* sp   = si + NN;            // 1024
    int* sb   = si + NN + 1024;     // 1024
    const int t = threadIdx.x;
    for (int i = t; i < NN; i += SCAN_T) { sdeg[i] = g_deg[i]; g_deg[i] = 0; }
    __syncthreads();
    const int base = t * CHUNK;
    int sum = 0;
#pragma unroll
    for (int i = 0; i < CHUNK; i++) {
        const int idx = base + i;
        if (idx < NN) {
            const int d = sdeg[idx];
            sdeg[idx] = sum;        // exclusive prefix within chunk
            sum += d;
        }
    }
    sp[t] = sum;
    __syncthreads();
    for (int o = 1; o < SCAN_T; o <<= 1) {
        int v = 0;
        if (t >= o) v = sp[t - o];
        __syncthreads();
        if (t >= o) sp[t] += v;
        __syncthreads();
    }
    sb[t] = sp[t] - sum;            // exclusive base per chunk
    __syncthreads();
    for (int i = t; i < NN; i += SCAN_T) {
        const int v = sdeg[i] + sb[i / CHUNK];
        g_off[i] = v;
        g_cur[i] = v;
    }
    if (t == SCAN_T - 1) g_off[NN] = sp[SCAN_T - 1];
}
#define SCAN_SMEM ((NN + 2 * SCAN_T) * 4)

// ================= pre2: scatterF + layer-0 el/er (fused) ===================
#define B_SCAT 391     // ceil(NE/256)
#define B_NA   313     // ceil(NN/64)
__global__ __launch_bounds__(256) void pre2_kernel(
        const int* __restrict__ dst, const int* __restrict__ src,
        const float* __restrict__ ef, const float* __restrict__ x)
{
    __shared__ float smf[64 * 65];
    const int t = threadIdx.x;
    const int b = blockIdx.x;
    if (b < B_SCAT) {
        // ---- scatter + gather + 4-layer ee
        float* srd = smf;                       // [4][NH*EFD] = 256
        if (t < 4 * NH * EFD) srd[t] = ((const float*)g_rede)[t];
        __syncthreads();
        const int e = b * 256 + t;
        if (e >= NE) return;
        const int pos = atomicAdd(&g_cur[dst[e]], 1);
        g_srcs[pos] = src[e];
        float r[EFD];
#pragma unroll
        for (int q = 0; q < EFD / 4; q++) {
            const float4 v = __ldg((const float4*)&ef[(size_t)e * EFD + q * 4]);
            r[q * 4 + 0] = v.x; r[q * 4 + 1] = v.y;
            r[q * 4 + 2] = v.z; r[q * 4 + 3] = v.w;
            *(float4*)&g_efs[(size_t)pos * EFD + q * 4] = v;
        }
#pragma unroll
        for (int lid = 0; lid < 4; lid++) {
            float v0 = 0.f, v1 = 0.f;
#pragma unroll
            for (int k = 0; k < EFD; k++) {
                v0 = fmaf(r[k], srd[lid * 64 + k], v0);
                v1 = fmaf(r[k], srd[lid * 64 + EFD + k], v1);
            }
            *(float2*)&g_eeall[lid][(size_t)pos * NH] = make_float2(v0, v1);
        }
    } else {
        // ---- layer-0 el/er for 64 nodes
        const int n0 = (b - B_SCAT) * 64;
        for (int i = t; i < 64 * NF; i += 256) {
            const int row = i >> 6, col = i & 63;
            const int n = n0 + row;
            smf[row * 65 + col] = (n < NN) ? x[(size_t)n * NF + col] : 0.f;
        }
        __syncthreads();
        const int type = t >> 7, h = (t >> 6) & 1, i = t & 63;
        const int n = n0 + i;
        if (n < NN) {
            const float* rd = (type ? g_redr : g_redl)[0] + h * NF;
            float v = 0.f;
#pragma unroll
            for (int k = 0; k < NF; k++) v = fmaf(smf[i * 65 + k], rd[k], v);
            (type ? g_erb : g_elb)[0][n * NH + h] = v;
        }
    }
}

// ================= per-layer kernels ========================================

// fused softmax + weighted-input aggregation. warp per dst node, x4 batched.
__global__ __launch_bounds__(256) void agg_kernel(
        const float* __restrict__ x,
        const float* __restrict__ el_in, const float* __restrict__ er_in,
        int lid)
{
    const int t = threadIdx.x;
    const int wid = t >> 5, lane = t & 31;
    const int n = blockIdx.x * 8 + wid;
    const float2 er2 = *(const float2*)&er_in[n * NH];
    const int start = g_off[n], end = g_off[n + 1];
    const int xoff = (lane & 15) * 4;
    const float* eep = g_eeall[lid];

    float4 xa = make_float4(0.f, 0.f, 0.f, 0.f);
    float u0 = 0.f, u1 = 0.f, s0 = 0.f, s1 = 0.f;

    int j = start;
    for (; j + 4 <= end; j += 4) {
        int sn[4]; float2 ee[4], el[4]; float4 xv[4]; float ev[4];
#pragma unroll
        for (int q = 0; q < 4; q++) sn[q] = g_srcs[j + q];
#pragma unroll
        for (int q = 0; q < 4; q++) {
            ee[q] = *(const float2*)&eep[(size_t)(j + q) * NH];
            el[q] = *(const float2*)&el_in[sn[q] * NH];
            xv[q] = __ldg((const float4*)&x[(size_t)sn[q] * NF + xoff]);
            ev[q] = g_efs[(size_t)(j + q) * EFD + lane];
        }
#pragma unroll
        for (int q = 0; q < 4; q++) {
            float l0 = el[q].x + er2.x + ee[q].x;
            float l1 = el[q].y + er2.y + ee[q].y;
            l0 = (l0 > 0.f) ? l0 : 0.2f * l0;
            l1 = (l1 > 0.f) ? l1 : 0.2f * l1;
            const float p0 = __expf(l0), p1 = __expf(l1);
            s0 += p0; s1 += p1;
            const float ph = (lane < 16) ? p0 : p1;
            xa.x = fmaf(xv[q].x, ph, xa.x);
            xa.y = fmaf(xv[q].y, ph, xa.y);
            xa.z = fmaf(xv[q].z, ph, xa.z);
            xa.w = fmaf(xv[q].w, ph, xa.w);
            u0 = fmaf(ev[q], p0, u0);
            u1 = fmaf(ev[q], p1, u1);
        }
    }
    for (; j < end; j++) {
        const int sn = g_srcs[j];
        const float2 ee = *(const float2*)&eep[(size_t)j * NH];
        const float2 el2 = *(const float2*)&el_in[sn * NH];
        float l0 = el2.x + er2.x + ee.x;
        float l1 = el2.y + er2.y + ee.y;
        l0 = (l0 > 0.f) ? l0 : 0.2f * l0;
        l1 = (l1 > 0.f) ? l1 : 0.2f * l1;
        const float p0 = __expf(l0), p1 = __expf(l1);
        s0 += p0; s1 += p1;
        const float ph = (lane < 16) ? p0 : p1;
        const float4 x4 = __ldg((const float4*)&x[(size_t)sn * NF + xoff]);
        const float efv = g_efs[(size_t)j * EFD + lane];
        xa.x = fmaf(x4.x, ph, xa.x);
        xa.y = fmaf(x4.y, ph, xa.y);
        xa.z = fmaf(x4.z, ph, xa.z);
        xa.w = fmaf(x4.w, ph, xa.w);
        u0 = fmaf(efv, p0, u0);
        u1 = fmaf(efv, p1, u1);
    }

    *(float4*)&g_xs[(size_t)n * FH + lane * 4] = xa;   // [0:64)=h0, [64:128)=h1
    g_us[n * 2 * EFD + lane] = u0;
    g_us[n * 2 * EFD + EFD + lane] = u1;
    if (lane == 0) {
        g_ss[n * NH + 0] = s0;
        g_ss[n * NH + 1] = s1;
    }
}

// finalize, 80 nodes/block (5 tiles of 16): weights staged ONCE per block.
// out = ((xs_h @ Wn_h) + (u_h @ We_h))/s_h + b, mean over heads;
// epilogue computes next layer's el/er from the fresh output rows.
__global__ __launch_bounds__(128) void fin_kernel(
        const float* __restrict__ Wn, const float* __restrict__ We,
        const float* __restrict__ b,
        float* __restrict__ el_out, float* __restrict__ er_out,
        int lid, int last, float* __restrict__ hout)
{
    const int c = threadIdx.x;                 // c = h*64 + d
    const int h = c >> 6;
    float wn[NF];
#pragma unroll
    for (int k = 0; k < NF; k++) wn[k] = Wn[k * FH + c];
    float we[EFD];
#pragma unroll
    for (int k = 0; k < EFD; k++) we[k] = We[k * FH + c];
    const float bc = b[c];

    __shared__ float sxs[16][FH];
    __shared__ float sus[16][2 * EFD];
    __shared__ float sss[16][NH];
    __shared__ float st [16][FH];

#pragma unroll 1
    for (int tile = 0; tile < 5; tile++) {
        const int n0 = blockIdx.x * 80 + tile * 16;
        for (int i = c; i < 16 * FH; i += 128)
            sxs[i >> 7][i & 127] = g_xs[(size_t)n0 * FH + i];
        for (int i = c; i < 16 * 2 * EFD; i += 128)
            sus[i >> 6][i & 63] = g_us[n0 * 2 * EFD + i];
        if (c < 16 * NH) sss[c >> 1][c & 1] = g_ss[n0 * NH + c];
        __syncthreads();

#pragma unroll 2
        for (int i = 0; i < 16; i++) {
            float a = 0.f;
#pragma unroll
            for (int k = 0; k < NF; k++) a = fmaf(sxs[i][h * NF + k], wn[k], a);
            float uu = 0.f;
#pragma unroll
            for (int k = 0; k < EFD; k++) uu = fmaf(sus[i][h * EFD + k], we[k], uu);
            const float s = sss[i][h];
            const float inv = (s > 0.f) ? 1.f / s : 0.f;   // deg-0 -> msg = 0
            st[i][c] = fmaf(a + uu, inv, bc);
        }
        __syncthreads();

        for (int i = c; i < 16 * DH; i += 128) {
            const int ni = i >> 6, d = i & 63;
            hout[(size_t)(n0 + ni) * DH + d] = 0.5f * (st[ni][d] + st[ni][DH + d]);
        }
        // next-layer el/er (64 tasks: type x head x 16 nodes)
        if (!last && c < 64) {
            const int type = c >> 5, hh = (c >> 4) & 1, i = c & 15;
            const float* rd = (type ? g_redr : g_redl)[lid + 1] + hh * NF;
            float v = 0.f;
#pragma unroll
            for (int d = 0; d < DH; d++)
                v = fmaf(0.5f * (st[i][d] + st[i][DH + d]), rd[d], v);
            (type ? er_out : el_out)[(n0 + i) * NH + hh] = v;
        }
        __syncthreads();
    }
}

// ---------------- host-side driver ------------------------------------------
extern "C" void kernel_launch(void* const* d_in, const int* in_sizes, int n_in,
                              void* d_out, int out_size)
{
    const float* x   = (const float*)d_in[0];
    const float* e   = (const float*)d_in[1];
    const int*   src = (const int*)  d_in[2];
    const int*   dst = (const int*)  d_in[3];

    // Only the LAST snapshot contributes to the output (decoded[-1]).
    const int S = in_sizes[0] / (NN * NF);
    const float* xs = x   + (size_t)(S - 1) * NN * NF;
    const float* es = e   + (size_t)(S - 1) * NE * EFD;
    const int*   ss = src + (size_t)(S - 1) * NE;
    const int*   ds = dst + (size_t)(S - 1) * NE;

    void *ph = nullptr, *ph2 = nullptr, *pwp = nullptr, *pel = nullptr, *per = nullptr;
    cudaGetSymbolAddress(&ph,  g_h);
    cudaGetSymbolAddress(&ph2, g_h2);
    cudaGetSymbolAddress(&pwp, g_Wp);
    cudaGetSymbolAddress(&pel, g_elb);
    cudaGetSymbolAddress(&per, g_erb);
    float* h  = (float*)ph;
    float* h2 = (float*)ph2;
    const float* Wp = (const float*)pwp;
    float* elb[2] = { (float*)pel, (float*)pel + NN * NH };
    float* erb[2] = { (float*)per, (float*)per + NN * NH };

    cudaFuncSetAttribute(scan_kernel, cudaFuncAttributeMaxDynamicSharedMemorySize,
                         SCAN_SMEM);

    // Input order (setup_inputs dict insertion order):
    //   0:x 1:e 2:src 3:dst, 4..9:enc0{Wn,We,al,ar,ae,b}, 10..15:enc1,
    //   16..21:dec0, 22..27:dec1, 28:W_e2d
    const float* P[29];
    for (int i = 4; i <= 28; i++) P[i] = (const float*)d_in[i];

    PrepParams pp;
    pp.Wn[0] = P[4];  pp.We[0] = P[5];  pp.al[0] = P[6];  pp.ar[0] = P[7];  pp.ae[0] = P[8];
    pp.Wn[1] = P[10]; pp.We[1] = P[11]; pp.al[1] = P[12]; pp.ar[1] = P[13]; pp.ae[1] = P[14];
    pp.Wn[2] = P[16]; pp.We[2] = P[17]; pp.al[2] = P[18]; pp.ar[2] = P[19]; pp.ae[2] = P[20];
    pp.Wn[3] = P[22]; pp.We[3] = P[23]; pp.al[3] = P[24]; pp.ar[3] = P[25]; pp.ae[3] = P[26];
    pp.We2d = P[28];

    pre1_kernel<<<B_HIST + B_WF + B_PREP, 256>>>(ds, pp);
    scan_kernel<<<1, SCAN_T, SCAN_SMEM>>>();
    pre2_kernel<<<B_SCAT + B_NA, 256>>>(ds, ss, es, xs);

    // layer 0 (enc0)
    agg_kernel<<<NN / 8, 256>>>(xs, elb[0], erb[0], 0);
    fin_kernel<<<NN / 80, 128>>>(P[4], P[5], P[9], elb[1], erb[1], 0, 0, h);
    // layer 1 (enc1)
    agg_kernel<<<NN / 8, 256>>>(h, elb[1], erb[1], 1);
    fin_kernel<<<NN / 80, 128>>>(P[10], P[11], P[15], elb[0], erb[0], 1, 0, h2);
    // layer 2 (dec0, e2d fused via Wp)
    agg_kernel<<<NN / 8, 256>>>(h2, elb[0], erb[0], 2);
    fin_kernel<<<NN / 80, 128>>>(Wp, P[17], P[21], elb[1], erb[1], 2, 0, h);
    // layer 3 (dec1)
    agg_kernel<<<NN / 8, 256>>>(h, elb[1], erb[1], 3);
    fin_kernel<<<NN / 80, 128>>>(P[22], P[23], P[27], elb[0], erb[0], 3, 1, (float*)d_out);
}

// round 10
// speedup vs baseline: 1.1403x; 1.0544x over previous
#include <cuda_runtime.h>

#define NN 20000      // nodes
#define NE 100000     // edges
#define NF 64         // node feature dim (in) — 64 for every layer here
#define EFD 32        // edge feature dim
#define FH 128        // heads * out_dim = 2*64
#define NH 2          // heads
#define DH 64         // out dim per head

// ---------------- scratch (device globals) ----------------------------------
__device__ __align__(16) float g_elb[2][NN * NH]; // double-buffered el
__device__ __align__(16) float g_erb[2][NN * NH]; // double-buffered er
__device__ __align__(16) float g_h [NN * NF];
__device__ __align__(16) float g_h2[NN * NF];
__device__ __align__(16) float g_Wp[NF * FH];     // W_e2d^T @ Wn_dec0
__device__ __align__(16) float g_efs[NE * EFD];   // ef rows in CSR order
__device__ __align__(8)  float g_eeall[4][NE * NH]; // ee per layer, CSR order
__device__ int g_srcs[NE];                        // src in CSR order
// reduced attention weights per layer
__device__ float g_redl[4][NH * NF];
__device__ float g_redr[4][NH * NF];
__device__ float g_rede[4][NH * EFD];
// CSR (dst -> edges)
__device__ int g_deg[NN];        // zero-init at load; scan re-zeroes each call
__device__ int g_off[NN + 1];
__device__ int g_cur[NN];

struct PrepParams {
    const float *Wn[4], *We[4], *al[4], *ar[4], *ae[4];
    const float* We2d;
};

// ================= pre1: hist + wfuse + prep (fused) ========================
#define B_HIST 391     // ceil(NE/256)
#define B_WF   32      // NF*FH/256
#define B_PREP 12      // 4 layers * 3 matrices
__global__ __launch_bounds__(256) void pre1_kernel(
        const int* __restrict__ dst, PrepParams pp)
{
    const int t = threadIdx.x;
    const int b = blockIdx.x;
    if (b < B_HIST) {                              // ---- histogram
        const int e = b * 256 + t;
        if (e < NE) atomicAdd(&g_deg[dst[e]], 1);
    } else if (b < B_HIST + B_WF) {                // ---- Wp = W_e2d^T @ Wn_dec0
        const int i = (b - B_HIST) * 256 + t;      // m*128 + c
        const int m = i >> 7, c = i & 127;
        float v = 0.f;
#pragma unroll
        for (int k = 0; k < NF; k++)
            v = fmaf(pp.We2d[k * NF + m], pp.Wn[2][k * FH + c], v);
        g_Wp[m * FH + c] = v;
    } else {                                       // ---- reduced attn weights
        const int bid2 = b - B_HIST - B_WF;
        const int lid = bid2 / 3, mat = bid2 % 3;
        __shared__ float stt[128];
        if (mat < 2) {                             // redl / redr
            const float* a = mat ? pp.ar[lid] : pp.al[lid];
            float v = 0.f;
            if (t < 128) {
                const int h = t >> 6, k = t & 63;
#pragma unroll
                for (int d = 0; d < DH; d++)
                    v = fmaf(pp.Wn[lid][k * FH + h * DH + d], a[h * DH + d], v);
                if (lid == 2) stt[t] = v;          // two-step for dec0 (e2d fused)
                else (mat ? g_redr : g_redl)[lid][(t >> 6) * NF + (t & 63)] = v;
            }
            if (lid == 2) {
                __syncthreads();
                if (t < 128) {
                    const int h = t >> 6, m = t & 63;
                    float w = 0.f;
#pragma unroll
                    for (int k = 0; k < NF; k++)
                        w = fmaf(pp.We2d[k * NF + m], stt[h * 64 + k], w);
                    (mat ? g_redr : g_redl)[2][h * NF + m] = w;
                }
            }
        } else if (t < NH * EFD) {                 // rede
            const int h = t >> 5, k = t & 31;
            float v = 0.f;
#pragma unroll
            for (int d = 0; d < DH; d++)
                v = fmaf(pp.We[lid][k * FH + h * DH + d], pp.ae[lid][h * DH + d], v);
            g_rede[lid][h * EFD + k] = v;
        }
    }
}

// ================= scan: smem-staged coalesced prefix sum ====================
#define SCAN_T 1024
#define CHUNK 20
__global__ __launch_bounds__(SCAN_T) void scan_kernel()
{
    extern __shared__ int si[];
    int* sdeg = si;                 // NN
    int* sp   = si + NN;            // 1024
    int* sb   = si + NN + 1024;     // 1024
    const int t = threadIdx.x;
    for (int i = t; i < NN; i += SCAN_T) { sdeg[i] = g_deg[i]; g_deg[i] = 0; }
    __syncthreads();
    const int base = t * CHUNK;
    int sum = 0;
#pragma unroll
    for (int i = 0; i < CHUNK; i++) {
        const int idx = base + i;
        if (idx < NN) {
            const int d = sdeg[idx];
            sdeg[idx] = sum;        // exclusive prefix within chunk
            sum += d;
        }
    }
    sp[t] = sum;
    __syncthreads();
    for (int o = 1; o < SCAN_T; o <<= 1) {
        int v = 0;
        if (t >= o) v = sp[t - o];
        __syncthreads();
        if (t >= o) sp[t] += v;
        __syncthreads();
    }
    sb[t] = sp[t] - sum;            // exclusive base per chunk
    __syncthreads();
    for (int i = t; i < NN; i += SCAN_T) {
        const int v = sdeg[i] + sb[i / CHUNK];
        g_off[i] = v;
        g_cur[i] = v;
    }
    if (t == SCAN_T - 1) g_off[NN] = sp[SCAN_T - 1];
}
#define SCAN_SMEM ((NN + 2 * SCAN_T) * 4)

// ================= pre2: scatterF + layer-0 el/er (fused) ===================
#define B_SCAT 391     // ceil(NE/256)
#define B_NA   313     // ceil(NN/64)
__global__ __launch_bounds__(256) void pre2_kernel(
        const int* __restrict__ dst, const int* __restrict__ src,
        const float* __restrict__ ef, const float* __restrict__ x)
{
    __shared__ float smf[64 * 65];
    const int t = threadIdx.x;
    const int b = blockIdx.x;
    if (b < B_SCAT) {
        // ---- scatter + gather + 4-layer ee
        float* srd = smf;                       // [4][NH*EFD] = 256
        if (t < 4 * NH * EFD) srd[t] = ((const float*)g_rede)[t];
        __syncthreads();
        const int e = b * 256 + t;
        if (e >= NE) return;
        const int pos = atomicAdd(&g_cur[dst[e]], 1);
        g_srcs[pos] = src[e];
        float r[EFD];
#pragma unroll
        for (int q = 0; q < EFD / 4; q++) {
            const float4 v = __ldg((const float4*)&ef[(size_t)e * EFD + q * 4]);
            r[q * 4 + 0] = v.x; r[q * 4 + 1] = v.y;
            r[q * 4 + 2] = v.z; r[q * 4 + 3] = v.w;
            *(float4*)&g_efs[(size_t)pos * EFD + q * 4] = v;
        }
#pragma unroll
        for (int lid = 0; lid < 4; lid++) {
            float v0 = 0.f, v1 = 0.f;
#pragma unroll
            for (int k = 0; k < EFD; k++) {
                v0 = fmaf(r[k], srd[lid * 64 + k], v0);
                v1 = fmaf(r[k], srd[lid * 64 + EFD + k], v1);
            }
            *(float2*)&g_eeall[lid][(size_t)pos * NH] = make_float2(v0, v1);
        }
    } else {
        // ---- layer-0 el/er for 64 nodes
        const int n0 = (b - B_SCAT) * 64;
        for (int i = t; i < 64 * NF; i += 256) {
            const int row = i >> 6, col = i & 63;
            const int n = n0 + row;
            smf[row * 65 + col] = (n < NN) ? x[(size_t)n * NF + col] : 0.f;
        }
        __syncthreads();
        const int type = t >> 7, h = (t >> 6) & 1, i = t & 63;
        const int n = n0 + i;
        if (n < NN) {
            const float* rd = (type ? g_redr : g_redl)[0] + h * NF;
            float v = 0.f;
#pragma unroll
            for (int k = 0; k < NF; k++) v = fmaf(smf[i * 65 + k], rd[k], v);
            (type ? g_erb : g_elb)[0][n * NH + h] = v;
        }
    }
}

// ================= fused per-layer kernel ====================================
// 256 threads, 8 nodes/block.
// Phase A: warp per dst node, x4-batched edge loop; lane owns 2 x-columns,
//          accumulates BOTH heads (halves gather traffic vs duplicate reads).
// Phase B: output GEMM t = ((xs_h@Wn_h)+(us_h@We_h))/s_h + b from smem,
//          weights via __ldg (L1-hot).
// Phase C: head-mean -> hout; next-layer el/er epilogue.
__global__ __launch_bounds__(256) void layer_kernel(
        const float* __restrict__ x,
        const float* __restrict__ Wn, const float* __restrict__ We,
        const float* __restrict__ b,
        const float* __restrict__ el_in, const float* __restrict__ er_in,
        float* __restrict__ el_out, float* __restrict__ er_out,
        int lid, int last, float* __restrict__ hout)
{
    __shared__ float sxs[8][FH];
    __shared__ float sus[8][2 * EFD];
    __shared__ float sss[8][NH];
    __shared__ float st [8][FH];

    const int t = threadIdx.x;
    const int wid = t >> 5, lane = t & 31;
    const int n0 = blockIdx.x * 8;
    const int n = n0 + wid;
    const float2 er2 = *(const float2*)&er_in[n * NH];
    const int start = g_off[n], end = g_off[n + 1];
    const float* eep = g_eeall[lid];

    float2 xa0 = make_float2(0.f, 0.f);   // head-0 weighted x sums (2 cols)
    float2 xa1 = make_float2(0.f, 0.f);   // head-1
    float u0 = 0.f, u1 = 0.f, s0 = 0.f, s1 = 0.f;

    int j = start;
    for (; j + 4 <= end; j += 4) {
        int sn[4]; float2 ee[4], el[4], xv[4]; float ev[4];
#pragma unroll
        for (int q = 0; q < 4; q++) sn[q] = g_srcs[j + q];
#pragma unroll
        for (int q = 0; q < 4; q++) {
            ee[q] = *(const float2*)&eep[(size_t)(j + q) * NH];
            el[q] = *(const float2*)&el_in[sn[q] * NH];
            xv[q] = __ldg((const float2*)&x[(size_t)sn[q] * NF + lane * 2]);
            ev[q] = g_efs[(size_t)(j + q) * EFD + lane];
        }
#pragma unroll
        for (int q = 0; q < 4; q++) {
            float l0 = el[q].x + er2.x + ee[q].x;
            float l1 = el[q].y + er2.y + ee[q].y;
            l0 = (l0 > 0.f) ? l0 : 0.2f * l0;
            l1 = (l1 > 0.f) ? l1 : 0.2f * l1;
            const float p0 = __expf(l0), p1 = __expf(l1);
            s0 += p0; s1 += p1;
            xa0.x = fmaf(xv[q].x, p0, xa0.x);
            xa0.y = fmaf(xv[q].y, p0, xa0.y);
            xa1.x = fmaf(xv[q].x, p1, xa1.x);
            xa1.y = fmaf(xv[q].y, p1, xa1.y);
            u0 = fmaf(ev[q], p0, u0);
            u1 = fmaf(ev[q], p1, u1);
        }
    }
    for (; j < end; j++) {
        const int sn = g_srcs[j];
        const float2 ee = *(const float2*)&eep[(size_t)j * NH];
        const float2 el2 = *(const float2*)&el_in[sn * NH];
        float l0 = el2.x + er2.x + ee.x;
        float l1 = el2.y + er2.y + ee.y;
        l0 = (l0 > 0.f) ? l0 : 0.2f * l0;
        l1 = (l1 > 0.f) ? l1 : 0.2f * l1;
        const float p0 = __expf(l0), p1 = __expf(l1);
        s0 += p0; s1 += p1;
        const float2 xv = __ldg((const float2*)&x[(size_t)sn * NF + lane * 2]);
        const float efv = g_efs[(size_t)j * EFD + lane];
        xa0.x = fmaf(xv.x, p0, xa0.x);
        xa0.y = fmaf(xv.y, p0, xa0.y);
        xa1.x = fmaf(xv.x, p1, xa1.x);
        xa1.y = fmaf(xv.y, p1, xa1.y);
        u0 = fmaf(efv, p0, u0);
        u1 = fmaf(efv, p1, u1);
    }

    *(float2*)&sxs[wid][lane * 2] = xa0;        // head0 cols [0:64)
    *(float2*)&sxs[wid][64 + lane * 2] = xa1;   // head1 cols [64:128)
    sus[wid][lane] = u0;
    sus[wid][32 + lane] = u1;
    if (lane == 0) { sss[wid][0] = s0; sss[wid][1] = s1; }
    __syncthreads();

    // Phase B: 8*128 outputs, 4 per thread; c is constant across reps
    {
        const int c = t & 127, h = c >> 6;
        const int i0 = t >> 7;                  // 0 or 1
#pragma unroll
        for (int rep = 0; rep < 4; rep++) {
            const int i = rep * 2 + i0;
            float a = 0.f;
#pragma unroll
            for (int k = 0; k < NF; k++)
                a = fmaf(sxs[i][h * NF + k], __ldg(&Wn[k * FH + c]), a);
            float uu = 0.f;
#pragma unroll
            for (int k = 0; k < EFD; k++)
                uu = fmaf(sus[i][h * EFD + k], __ldg(&We[k * FH + c]), uu);
            const float s = sss[i][h];
            const float inv = (s > 0.f) ? 1.f / s : 0.f;   // deg-0 -> msg = 0
            st[i][c] = fmaf(a + uu, inv, __ldg(&b[c]));
        }
    }
    __syncthreads();

    // Phase C: head mean -> hout (8*64 outputs, 2 per thread)
#pragma unroll
    for (int rep = 0; rep < 2; rep++) {
        const int idx = rep * 256 + t;
        const int i = idx >> 6, d = idx & 63;
        hout[(size_t)(n0 + i) * DH + d] = 0.5f * (st[i][d] + st[i][DH + d]);
    }
    // next-layer el/er (32 tasks: type x head x 8 nodes)
    if (!last && t < 32) {
        const int type = t >> 4, hh = (t >> 3) & 1, i = t & 7;
        const float* rd = (type ? g_redr : g_redl)[lid + 1] + hh * NF;
        float v = 0.f;
#pragma unroll
        for (int d = 0; d < DH; d++)
            v = fmaf(0.5f * (st[i][d] + st[i][DH + d]), rd[d], v);
        (type ? er_out : el_out)[(n0 + i) * NH + hh] = v;
    }
}

// ---------------- host-side driver ------------------------------------------
extern "C" void kernel_launch(void* const* d_in, const int* in_sizes, int n_in,
                              void* d_out, int out_size)
{
    const float* x   = (const float*)d_in[0];
    const float* e   = (const float*)d_in[1];
    const int*   src = (const int*)  d_in[2];
    const int*   dst = (const int*)  d_in[3];

    // Only the LAST snapshot contributes to the output (decoded[-1]).
    const int S = in_sizes[0] / (NN * NF);
    const float* xs = x   + (size_t)(S - 1) * NN * NF;
    const float* es = e   + (size_t)(S - 1) * NE * EFD;
    const int*   ss = src + (size_t)(S - 1) * NE;
    const int*   ds = dst + (size_t)(S - 1) * NE;

    void *ph = nullptr, *ph2 = nullptr, *pwp = nullptr, *pel = nullptr, *per = nullptr;
    cudaGetSymbolAddress(&ph,  g_h);
    cudaGetSymbolAddress(&ph2, g_h2);
    cudaGetSymbolAddress(&pwp, g_Wp);
    cudaGetSymbolAddress(&pel, g_elb);
    cudaGetSymbolAddress(&per, g_erb);
    float* h  = (float*)ph;
    float* h2 = (float*)ph2;
    const float* Wp = (const float*)pwp;
    float* elb[2] = { (float*)pel, (float*)pel + NN * NH };
    float* erb[2] = { (float*)per, (float*)per + NN * NH };

    cudaFuncSetAttribute(scan_kernel, cudaFuncAttributeMaxDynamicSharedMemorySize,
                         SCAN_SMEM);

    // Input order (setup_inputs dict insertion order):
    //   0:x 1:e 2:src 3:dst, 4..9:enc0{Wn,We,al,ar,ae,b}, 10..15:enc1,
    //   16..21:dec0, 22..27:dec1, 28:W_e2d
    const float* P[29];
    for (int i = 4; i <= 28; i++) P[i] = (const float*)d_in[i];

    PrepParams pp;
    pp.Wn[0] = P[4];  pp.We[0] = P[5];  pp.al[0] = P[6];  pp.ar[0] = P[7];  pp.ae[0] = P[8];
    pp.Wn[1] = P[10]; pp.We[1] = P[11]; pp.al[1] = P[12]; pp.ar[1] = P[13]; pp.ae[1] = P[14];
    pp.Wn[2] = P[16]; pp.We[2] = P[17]; pp.al[2] = P[18]; pp.ar[2] = P[19]; pp.ae[2] = P[20];
    pp.Wn[3] = P[22]; pp.We[3] = P[23]; pp.al[3] = P[24]; pp.ar[3] = P[25]; pp.ae[3] = P[26];
    pp.We2d = P[28];

    pre1_kernel<<<B_HIST + B_WF + B_PREP, 256>>>(ds, pp);
    scan_kernel<<<1, SCAN_T, SCAN_SMEM>>>();
    pre2_kernel<<<B_SCAT + B_NA, 256>>>(ds, ss, es, xs);

    layer_kernel<<<NN / 8, 256>>>(xs, P[4],  P[5],  P[9],
                                  elb[0], erb[0], elb[1], erb[1], 0, 0, h);
    layer_kernel<<<NN / 8, 256>>>(h,  P[10], P[11], P[15],
                                  elb[1], erb[1], elb[0], erb[0], 1, 0, h2);
    layer_kernel<<<NN / 8, 256>>>(h2, Wp,    P[17], P[21],
                                  elb[0], erb[0], elb[1], erb[1], 2, 0, h);
    layer_kernel<<<NN / 8, 256>>>(h,  P[22], P[23], P[27],
                                  elb[1], erb[1], elb[0], erb[0], 3, 1, (float*)d_out);
}

// round 11
// speedup vs baseline: 1.4744x; 1.2929x over previous
#include <cuda_runtime.h>

#define NN 20000      // nodes
#define NE 100000     // edges
#define NF 64         // node feature dim (in) — 64 for every layer here
#define EFD 32        // edge feature dim
#define FH 128        // heads * out_dim = 2*64
#define NH 2          // heads
#define DH 64         // out dim per head

// ---------------- scratch (device globals) ----------------------------------
__device__ __align__(16) float g_elb[2][NN * NH]; // double-buffered el
__device__ __align__(16) float g_erb[2][NN * NH]; // double-buffered er
__device__ __align__(16) float g_h [NN * NF];
__device__ __align__(16) float g_h2[NN * NF];
__device__ __align__(16) float g_Wp[NF * FH];     // W_e2d^T @ Wn_dec0
__device__ __align__(16) float g_efs[NE * EFD];   // ef rows in CSR order
__device__ __align__(8)  float g_eeall[4][NE * NH]; // ee per layer, CSR order
__device__ int g_srcs[NE];                        // src in CSR order
// reduced attention weights per layer
__device__ float g_redl[4][NH * NF];
__device__ float g_redr[4][NH * NF];
__device__ float g_rede[4][NH * EFD];
// CSR (dst -> edges)
__device__ int g_deg[NN];        // zero-init at load; scan re-zeroes each call
__device__ int g_off[NN + 1];
__device__ int g_cur[NN];

struct PrepParams {
    const float *Wn[4], *We[4], *al[4], *ar[4], *ae[4];
    const float* We2d;
};

// ================= pre1: hist + wfuse + prep (fused) ========================
#define B_HIST 391     // ceil(NE/256)
#define B_WF   32      // NF*FH/256
#define B_PREP 12      // 4 layers * 3 matrices
__global__ __launch_bounds__(256) void pre1_kernel(
        const int* __restrict__ dst, PrepParams pp)
{
    const int t = threadIdx.x;
    const int b = blockIdx.x;
    if (b < B_HIST) {                              // ---- histogram
        const int e = b * 256 + t;
        if (e < NE) atomicAdd(&g_deg[dst[e]], 1);
    } else if (b < B_HIST + B_WF) {                // ---- Wp = W_e2d^T @ Wn_dec0
        const int i = (b - B_HIST) * 256 + t;      // m*128 + c
        const int m = i >> 7, c = i & 127;
        float v = 0.f;
#pragma unroll
        for (int k = 0; k < NF; k++)
            v = fmaf(pp.We2d[k * NF + m], pp.Wn[2][k * FH + c], v);
        g_Wp[m * FH + c] = v;
    } else {                                       // ---- reduced attn weights
        const int bid2 = b - B_HIST - B_WF;
        const int lid = bid2 / 3, mat = bid2 % 3;
        __shared__ float stt[128];
        if (mat < 2) {                             // redl / redr
            const float* a = mat ? pp.ar[lid] : pp.al[lid];
            float v = 0.f;
            if (t < 128) {
                const int h = t >> 6, k = t & 63;
#pragma unroll
                for (int d = 0; d < DH; d++)
                    v = fmaf(pp.Wn[lid][k * FH + h * DH + d], a[h * DH + d], v);
                if (lid == 2) stt[t] = v;          // two-step for dec0 (e2d fused)
                else (mat ? g_redr : g_redl)[lid][(t >> 6) * NF + (t & 63)] = v;
            }
            if (lid == 2) {
                __syncthreads();
                if (t < 128) {
                    const int h = t >> 6, m = t & 63;
                    float w = 0.f;
#pragma unroll
                    for (int k = 0; k < NF; k++)
                        w = fmaf(pp.We2d[k * NF + m], stt[h * 64 + k], w);
                    (mat ? g_redr : g_redl)[2][h * NF + m] = w;
                }
            }
        } else if (t < NH * EFD) {                 // rede
            const int h = t >> 5, k = t & 31;
            float v = 0.f;
#pragma unroll
            for (int d = 0; d < DH; d++)
                v = fmaf(pp.We[lid][k * FH + h * DH + d], pp.ae[lid][h * DH + d], v);
            g_rede[lid][h * EFD + k] = v;
        }
    }
}

// ================= scan: smem-staged coalesced prefix sum ====================
#define SCAN_T 1024
#define CHUNK 20
__global__ __launch_bounds__(SCAN_T) void scan_kernel()
{
    extern __shared__ int si[];
    int* sdeg = si;                 // NN
    int* sp   = si + NN;            // 1024
    int* sb   = si + NN + 1024;     // 1024
    const int t = threadIdx.x;
    for (int i = t; i < NN; i += SCAN_T) { sdeg[i] = g_deg[i]; g_deg[i] = 0; }
    __syncthreads();
    const int base = t * CHUNK;
    int sum = 0;
#pragma unroll
    for (int i = 0; i < CHUNK; i++) {
        const int idx = base + i;
        if (idx < NN) {
            const int d = sdeg[idx];
            sdeg[idx] = sum;        // exclusive prefix within chunk
            sum += d;
        }
    }
    sp[t] = sum;
    __syncthreads();
    for (int o = 1; o < SCAN_T; o <<= 1) {
        int v = 0;
        if (t >= o) v = sp[t - o];
        __syncthreads();
        if (t >= o) sp[t] += v;
        __syncthreads();
    }
    sb[t] = sp[t] - sum;            // exclusive base per chunk
    __syncthreads();
    for (int i = t; i < NN; i += SCAN_T) {
        const int v = sdeg[i] + sb[i / CHUNK];
        g_off[i] = v;
        g_cur[i] = v;
    }
    if (t == SCAN_T - 1) g_off[NN] = sp[SCAN_T - 1];
}
#define SCAN_SMEM ((NN + 2 * SCAN_T) * 4)

// ================= pre2: scatterF + layer-0 el/er (fused) ===================
#define B_SCAT 391     // ceil(NE/256)
#define B_NA   313     // ceil(NN/64)
__global__ __launch_bounds__(256) void pre2_kernel(
        const int* __restrict__ dst, const int* __restrict__ src,
        const float* __restrict__ ef, const float* __restrict__ x)
{
    __shared__ float smf[64 * 65];
    const int t = threadIdx.x;
    const int b = blockIdx.x;
    if (b < B_SCAT) {
        // ---- scatter + gather + 4-layer ee
        float* srd = smf;                       // [4][NH*EFD] = 256
        if (t < 4 * NH * EFD) srd[t] = ((const float*)g_rede)[t];
        __syncthreads();
        const int e = b * 256 + t;
        if (e >= NE) return;
        const int pos = atomicAdd(&g_cur[dst[e]], 1);
        g_srcs[pos] = src[e];
        float r[EFD];
#pragma unroll
        for (int q = 0; q < EFD / 4; q++) {
            const float4 v = __ldg((const float4*)&ef[(size_t)e * EFD + q * 4]);
            r[q * 4 + 0] = v.x; r[q * 4 + 1] = v.y;
            r[q * 4 + 2] = v.z; r[q * 4 + 3] = v.w;
            *(float4*)&g_efs[(size_t)pos * EFD + q * 4] = v;
        }
#pragma unroll
        for (int lid = 0; lid < 4; lid++) {
            float v0 = 0.f, v1 = 0.f;
#pragma unroll
            for (int k = 0; k < EFD; k++) {
                v0 = fmaf(r[k], srd[lid * 64 + k], v0);
                v1 = fmaf(r[k], srd[lid * 64 + EFD + k], v1);
            }
            *(float2*)&g_eeall[lid][(size_t)pos * NH] = make_float2(v0, v1);
        }
    } else {
        // ---- layer-0 el/er for 64 nodes
        const int n0 = (b - B_SCAT) * 64;
        for (int i = t; i < 64 * NF; i += 256) {
            const int row = i >> 6, col = i & 63;
            const int n = n0 + row;
            smf[row * 65 + col] = (n < NN) ? x[(size_t)n * NF + col] : 0.f;
        }
        __syncthreads();
        const int type = t >> 7, h = (t >> 6) & 1, i = t & 63;
        const int n = n0 + i;
        if (n < NN) {
            const float* rd = (type ? g_redr : g_redl)[0] + h * NF;
            float v = 0.f;
#pragma unroll
            for (int k = 0; k < NF; k++) v = fmaf(smf[i * 65 + k], rd[k], v);
            (type ? g_erb : g_elb)[0][n * NH + h] = v;
        }
    }
}

// ================= fused per-layer kernel ====================================
// 256 threads, 8 nodes/block.
// Phase A: warp per dst node, x4-batched edge loop; lane owns 2 x-columns,
//          accumulates BOTH heads. Results stored TRANSPOSED in smem
//          (sA[k][i], sU[k][i], node i contiguous).
// Phase B: register-tiled output GEMM — each thread computes a 4-row x 1-col
//          micro-tile: per k, 1 weight LDG + 1 broadcast LDS.128 + 4 FMA
//          (loads/FMA = 0.5 vs 2.0 before).
// Phase C: head-mean -> hout; next-layer el/er epilogue.
__global__ __launch_bounds__(256) void layer_kernel(
        const float* __restrict__ x,
        const float* __restrict__ Wn, const float* __restrict__ We,
        const float* __restrict__ b,
        const float* __restrict__ el_in, const float* __restrict__ er_in,
        float* __restrict__ el_out, float* __restrict__ er_out,
        int lid, int last, float* __restrict__ hout)
{
    __shared__ __align__(16) float sA[FH * 8];       // sA[k][i] = xs_h[i][k], k=h*64+kk
    __shared__ __align__(16) float sU[2 * EFD * 8];  // sU[k][i] = us_h[i][k], k=h*32+kk
    __shared__ float sss[8 * NH];
    __shared__ float st [8 * FH];

    const int t = threadIdx.x;
    const int wid = t >> 5, lane = t & 31;
    const int n0 = blockIdx.x * 8;
    const int n = n0 + wid;
    const float2 er2 = *(const float2*)&er_in[n * NH];
    const int start = g_off[n], end = g_off[n + 1];
    const float* eep = g_eeall[lid];

    float2 xa0 = make_float2(0.f, 0.f);   // head-0 weighted x sums (2 cols)
    float2 xa1 = make_float2(0.f, 0.f);   // head-1
    float u0 = 0.f, u1 = 0.f, s0 = 0.f, s1 = 0.f;

    int j = start;
    for (; j + 4 <= end; j += 4) {
        int sn[4]; float2 ee[4], el[4], xv[4]; float ev[4];
#pragma unroll
        for (int q = 0; q < 4; q++) sn[q] = g_srcs[j + q];
#pragma unroll
        for (int q = 0; q < 4; q++) {
            ee[q] = *(const float2*)&eep[(size_t)(j + q) * NH];
            el[q] = *(const float2*)&el_in[sn[q] * NH];
            xv[q] = __ldg((const float2*)&x[(size_t)sn[q] * NF + lane * 2]);
            ev[q] = g_efs[(size_t)(j + q) * EFD + lane];
        }
#pragma unroll
        for (int q = 0; q < 4; q++) {
            float l0 = el[q].x + er2.x + ee[q].x;
            float l1 = el[q].y + er2.y + ee[q].y;
            l0 = (l0 > 0.f) ? l0 : 0.2f * l0;
            l1 = (l1 > 0.f) ? l1 : 0.2f * l1;
            const float p0 = __expf(l0), p1 = __expf(l1);
            s0 += p0; s1 += p1;
            xa0.x = fmaf(xv[q].x, p0, xa0.x);
            xa0.y = fmaf(xv[q].y, p0, xa0.y);
            xa1.x = fmaf(xv[q].x, p1, xa1.x);
            xa1.y = fmaf(xv[q].y, p1, xa1.y);
            u0 = fmaf(ev[q], p0, u0);
            u1 = fmaf(ev[q], p1, u1);
        }
    }
    for (; j < end; j++) {
        const int sn = g_srcs[j];
        const float2 ee = *(const float2*)&eep[(size_t)j * NH];
        const float2 el2 = *(const float2*)&el_in[sn * NH];
        float l0 = el2.x + er2.x + ee.x;
        float l1 = el2.y + er2.y + ee.y;
        l0 = (l0 > 0.f) ? l0 : 0.2f * l0;
        l1 = (l1 > 0.f) ? l1 : 0.2f * l1;
        const float p0 = __expf(l0), p1 = __expf(l1);
        s0 += p0; s1 += p1;
        const float2 xv = __ldg((const float2*)&x[(size_t)sn * NF + lane * 2]);
        const float efv = g_efs[(size_t)j * EFD + lane];
        xa0.x = fmaf(xv.x, p0, xa0.x);
        xa0.y = fmaf(xv.y, p0, xa0.y);
        xa1.x = fmaf(xv.x, p1, xa1.x);
        xa1.y = fmaf(xv.y, p1, xa1.y);
        u0 = fmaf(efv, p0, u0);
        u1 = fmaf(efv, p1, u1);
    }

    // transposed stores: sA[(h*64+k)*8 + i], sU[(h*32+k)*8 + i]
    sA[(lane * 2    ) * 8 + wid] = xa0.x;
    sA[(lane * 2 + 1) * 8 + wid] = xa0.y;
    sA[(64 + lane * 2    ) * 8 + wid] = xa1.x;
    sA[(64 + lane * 2 + 1) * 8 + wid] = xa1.y;
    sU[lane * 8 + wid] = u0;
    sU[(32 + lane) * 8 + wid] = u1;
    if (lane == 0) { sss[wid * 2] = s0; sss[wid * 2 + 1] = s1; }
    __syncthreads();

    // Phase B: 4-row x 1-col micro-tile per thread (1024 outputs = 256 x 4)
    {
        const int c = t & 127, h = c >> 6, rg = t >> 7;   // rg in {0,1}
        float a0 = 0.f, a1 = 0.f, a2 = 0.f, a3 = 0.f;
        const float* sAh = sA + (h * 64) * 8 + rg * 4;
#pragma unroll
        for (int k = 0; k < NF; k++) {
            const float w = __ldg(&Wn[k * FH + c]);
            const float4 xv = *(const float4*)&sAh[k * 8];
            a0 = fmaf(xv.x, w, a0);
            a1 = fmaf(xv.y, w, a1);
            a2 = fmaf(xv.z, w, a2);
            a3 = fmaf(xv.w, w, a3);
        }
        const float* sUh = sU + (h * 32) * 8 + rg * 4;
#pragma unroll
        for (int k = 0; k < EFD; k++) {
            const float w = __ldg(&We[k * FH + c]);
            const float4 uv = *(const float4*)&sUh[k * 8];
            a0 = fmaf(uv.x, w, a0);
            a1 = fmaf(uv.y, w, a1);
            a2 = fmaf(uv.z, w, a2);
            a3 = fmaf(uv.w, w, a3);
        }
        const float bc = __ldg(&b[c]);
        float acc[4] = { a0, a1, a2, a3 };
#pragma unroll
        for (int r = 0; r < 4; r++) {
            const int i = rg * 4 + r;
            const float s = sss[i * 2 + h];
            const float inv = (s > 0.f) ? 1.f / s : 0.f;   // deg-0 -> msg = 0
            st[i * FH + c] = fmaf(acc[r], inv, bc);
        }
    }
    __syncthreads();

    // Phase C: head mean -> hout (8*64 outputs, 2 per thread)
#pragma unroll
    for (int rep = 0; rep < 2; rep++) {
        const int idx = rep * 256 + t;
        const int i = idx >> 6, d = idx & 63;
        hout[(size_t)(n0 + i) * DH + d] = 0.5f * (st[i * FH + d] + st[i * FH + DH + d]);
    }
    // next-layer el/er (32 tasks: type x head x 8 nodes)
    if (!last && t < 32) {
        const int type = t >> 4, hh = (t >> 3) & 1, i = t & 7;
        const float* rd = (type ? g_redr : g_redl)[lid + 1] + hh * NF;
        float v = 0.f;
#pragma unroll
        for (int d = 0; d < DH; d++)
            v = fmaf(0.5f * (st[i * FH + d] + st[i * FH + DH + d]), rd[d], v);
        (type ? er_out : el_out)[(n0 + i) * NH + hh] = v;
    }
}

// ---------------- host-side driver ------------------------------------------
extern "C" void kernel_launch(void* const* d_in, const int* in_sizes, int n_in,
                              void* d_out, int out_size)
{
    const float* x   = (const float*)d_in[0];
    const float* e   = (const float*)d_in[1];
    const int*   src = (const int*)  d_in[2];
    const int*   dst = (const int*)  d_in[3];

    // Only the LAST snapshot contributes to the output (decoded[-1]).
    const int S = in_sizes[0] / (NN * NF);
    const float* xs = x   + (size_t)(S - 1) * NN * NF;
    const float* es = e   + (size_t)(S - 1) * NE * EFD;
    const int*   ss = src + (size_t)(S - 1) * NE;
    const int*   ds = dst + (size_t)(S - 1) * NE;

    void *ph = nullptr, *ph2 = nullptr, *pwp = nullptr, *pel = nullptr, *per = nullptr;
    cudaGetSymbolAddress(&ph,  g_h);
    cudaGetSymbolAddress(&ph2, g_h2);
    cudaGetSymbolAddress(&pwp, g_Wp);
    cudaGetSymbolAddress(&pel, g_elb);
    cudaGetSymbolAddress(&per, g_erb);
    float* h  = (float*)ph;
    float* h2 = (float*)ph2;
    const float* Wp = (const float*)pwp;
    float* elb[2] = { (float*)pel, (float*)pel + NN * NH };
    float* erb[2] = { (float*)per, (float*)per + NN * NH };

    cudaFuncSetAttribute(scan_kernel, cudaFuncAttributeMaxDynamicSharedMemorySize,
                         SCAN_SMEM);

    // Input order (setup_inputs dict insertion order):
    //   0:x 1:e 2:src 3:dst, 4..9:enc0{Wn,We,al,ar,ae,b}, 10..15:enc1,
    //   16..21:dec0, 22..27:dec1, 28:W_e2d
    const float* P[29];
    for (int i = 4; i <= 28; i++) P[i] = (const float*)d_in[i];

    PrepParams pp;
    pp.Wn[0] = P[4];  pp.We[0] = P[5];  pp.al[0] = P[6];  pp.ar[0] = P[7];  pp.ae[0] = P[8];
    pp.Wn[1] = P[10]; pp.We[1] = P[11]; pp.al[1] = P[12]; pp.ar[1] = P[13]; pp.ae[1] = P[14];
    pp.Wn[2] = P[16]; pp.We[2] = P[17]; pp.al[2] = P[18]; pp.ar[2] = P[19]; pp.ae[2] = P[20];
    pp.Wn[3] = P[22]; pp.We[3] = P[23]; pp.al[3] = P[24]; pp.ar[3] = P[25]; pp.ae[3] = P[26];
    pp.We2d = P[28];

    pre1_kernel<<<B_HIST + B_WF + B_PREP, 256>>>(ds, pp);
    scan_kernel<<<1, SCAN_T, SCAN_SMEM>>>();
    pre2_kernel<<<B_SCAT + B_NA, 256>>>(ds, ss, es, xs);

    layer_kernel<<<NN / 8, 256>>>(xs, P[4],  P[5],  P[9],
                                  elb[0], erb[0], elb[1], erb[1], 0, 0, h);
    layer_kernel<<<NN / 8, 256>>>(h,  P[10], P[11], P[15],
                                  elb[1], erb[1], elb[0], erb[0], 1, 0, h2);
    layer_kernel<<<NN / 8, 256>>>(h2, Wp,    P[17], P[21],
                                  elb[0], erb[0], elb[1], erb[1], 2, 0, h);
    layer_kernel<<<NN / 8, 256>>>(h,  P[22], P[23], P[27],
                                  elb[1], erb[1], elb[0], erb[0], 3, 1, (float*)d_out);
}